// round 9
// baseline (speedup 1.0000x reference)
#include <cuda_runtime.h>
#include <math.h>

#define B_  32
#define L_  4096
#define D_  1024
#define D4_ (D_ / 4)           // 256 float4 per row
#define NA_ 8
#define NCHUNK 32
#define LCHUNK (L_ / NCHUNK)   // 128
#define NW_ 8                  // warps per accum block

// Partial sums per (b, l-chunk, action, d). 33.6 MB scratch (L2-resident).
__device__ float g_part[B_ * NCHUNK * NA_ * D_];
// Per (b, l-chunk, action) masked counts.
__device__ int   g_cnt [B_ * NCHUNK * NA_];

// ---------------------------------------------------------------------------
// Kernel 1: masked segmented sum into per-chunk partials.
// grid = (NCHUNK, B) = 1024 blocks, 256 threads; thread owns one float4
// column. Rows stably partitioned by action via warp ballots; main loop is
// branchless with 4 loads in flight. 1024 blocks reduce the 3-vs-4
// blocks-per-SM straggler tail that capped the 512-block version.
// ---------------------------------------------------------------------------
__global__ __launch_bounds__(256, 6)
void accum_kernel(const float4* __restrict__ emb4,
                  const int* __restrict__ actions,
                  const int* __restrict__ mask)
{
    const int chunk = blockIdx.x;
    const int b     = blockIdx.y;
    const int tid   = threadIdx.x;
    const int l0    = chunk * LCHUNK;
    const int w     = tid >> 5, lane = tid & 31;

    __shared__ short s_order[LCHUNK];
    __shared__ int   s_wcnt[NA_ * NW_];
    __shared__ int   s_woff[NA_ * NW_ + 1];

    // mask is bool upcast to a 4-byte type by the harness; nonzero = True.
    int act = -1;
    if (tid < LCHUNK) {
        int a = actions[b * L_ + l0 + tid];
        int m = mask[b * L_ + l0 + tid];
        act = (m != 0) ? a : -1;
    }

    // Stable partition by action: warp ballots + popc ranks.
    const unsigned lt = (1u << lane) - 1u;
    int myrank = 0;
    #pragma unroll
    for (int aa = 0; aa < NA_; ++aa) {
        unsigned bal = __ballot_sync(0xffffffffu, act == aa);
        if (lane == 0) s_wcnt[aa * NW_ + w] = __popc(bal);
        if (act == aa) myrank = __popc(bal & lt);
    }
    __syncthreads();
    if (tid == 0) {
        int acc = 0;
        #pragma unroll
        for (int q = 0; q < NA_ * NW_; ++q) { s_woff[q] = acc; acc += s_wcnt[q]; }
        s_woff[NA_ * NW_] = acc;
    }
    __syncthreads();
    if (act >= 0) s_order[s_woff[act * NW_ + w] + myrank] = (short)tid;
    if (tid < NA_)
        g_cnt[(b * NCHUNK + chunk) * NA_ + tid] =
            s_woff[(tid + 1) * NW_] - s_woff[tid * NW_];
    __syncthreads();

    const float4* base = emb4 + ((size_t)b * L_ + l0) * D4_ + tid;
    float4* outp = reinterpret_cast<float4*>(g_part)
                   + (size_t)(b * NCHUNK + chunk) * NA_ * D4_ + tid;

    #pragma unroll 1
    for (int a = 0; a < NA_; ++a) {
        float4 acc = make_float4(0.f, 0.f, 0.f, 0.f);
        const int s = s_woff[a * NW_], e = s_woff[(a + 1) * NW_];
        int i = s;
        for (; i + 4 <= e; i += 4) {
            const float4 v0 = base[(int)s_order[i]     * D4_];
            const float4 v1 = base[(int)s_order[i + 1] * D4_];
            const float4 v2 = base[(int)s_order[i + 2] * D4_];
            const float4 v3 = base[(int)s_order[i + 3] * D4_];
            acc.x += (v0.x + v1.x) + (v2.x + v3.x);
            acc.y += (v0.y + v1.y) + (v2.y + v3.y);
            acc.z += (v0.z + v1.z) + (v2.z + v3.z);
            acc.w += (v0.w + v1.w) + (v2.w + v3.w);
        }
        for (; i < e; ++i) {
            const float4 v = base[(int)s_order[i] * D4_];
            acc.x += v.x; acc.y += v.y; acc.z += v.z; acc.w += v.w;
        }
        outp[a * D4_] = acc;
    }
}

// ---------------------------------------------------------------------------
// Kernel 2: head. grid = (NA, B) = 256 blocks, 1024 threads. Layer-1 uses
// float4 weight loads (4 neurons per thread) — 4x fewer L1 wavefronts at the
// same FLOPs, same thread count.
// ---------------------------------------------------------------------------
__global__ __launch_bounds__(1024)
void head_kernel(const float* __restrict__ sw1, const float* __restrict__ sb1,
                 const float* __restrict__ sw2, const float* __restrict__ sb2,
                 const float* __restrict__ ew1, const float* __restrict__ eb1,
                 const float* __restrict__ ew2, const float* __restrict__ eb2,
                 float* __restrict__ out)
{
    const int a   = blockIdx.x;
    const int b   = blockIdx.y;
    const int tid = threadIdx.x;

    __shared__ float s_feat[D_];       // 4 KB
    __shared__ float s_buf [4096];     // 16 KB (feats partials, then MLP1 partials)
    __shared__ float s_buf2[4096];     // 16 KB (effect-MLP partials)
    __shared__ float s_h1[128];
    __shared__ float s_eh[64];
    __shared__ float s_logit[14];
    __shared__ float s_eff[3];
    __shared__ float s_scal[2];        // [0] = inv_cnt, [1] = seen

    // ---- counts ----
    if (tid == 0) {
        int c = 0;
        #pragma unroll
        for (int ch = 0; ch < NCHUNK; ++ch)
            c += g_cnt[(b * NCHUNK + ch) * NA_ + a];
        s_scal[0] = 1.0f / fmaxf((float)c, 1.0f);
        s_scal[1] = (c > 0) ? 1.0f : 0.0f;
    }

    // ---- feats partials: col4 = tid&255, chunk-group cg = tid>>8 (4 groups) ----
    {
        const int col4 = tid & 255, cg = tid >> 8;
        const float4* gp4 = reinterpret_cast<const float4*>(g_part)
                            + ((size_t)b * NCHUNK * NA_ + a) * D4_ + col4;
        float4 s = make_float4(0.f, 0.f, 0.f, 0.f);
        #pragma unroll
        for (int ch = 0; ch < NCHUNK / 4; ++ch) {   // 8 chunks per group
            const float4 v = gp4[(size_t)(cg * (NCHUNK / 4) + ch) * NA_ * D4_];
            s.x += v.x; s.y += v.y; s.z += v.z; s.w += v.w;
        }
        reinterpret_cast<float4*>(s_buf)[cg * 256 + col4] = s;
    }
    __syncthreads();
    const float inv_cnt = s_scal[0];
    const float seen    = s_scal[1];
    {
        // element (cg, d) lives at s_buf[cg*1024 + d]
        float v = (s_buf[tid] + s_buf[1024 + tid])
                + (s_buf[2048 + tid] + s_buf[3072 + tid]);
        s_feat[tid] = v * inv_cnt;
    }
    __syncthreads();

    // ---- MLP1 layer 1 partials: 32 neuron-quads x 32 d-groups ----
    {
        const int n4 = tid & 31, g = tid >> 5;      // g in 0..31, 32 d each
        const float4* w4 = reinterpret_cast<const float4*>(sw1);
        float4 acc = make_float4(0.f, 0.f, 0.f, 0.f);
        #pragma unroll 4
        for (int i = 0; i < 32; ++i) {
            const int d = g * 32 + i;
            const float4 wv = w4[d * 32 + n4];
            const float  f  = s_feat[d];
            acc.x = fmaf(f, wv.x, acc.x);
            acc.y = fmaf(f, wv.y, acc.y);
            acc.z = fmaf(f, wv.z, acc.z);
            acc.w = fmaf(f, wv.w, acc.w);
        }
        reinterpret_cast<float4*>(s_buf)[g * 32 + n4] = acc;  // float idx g*128+n
    }
    // ---- effect MLP layer 1 partials: 16 neuron-quads x 64 d-groups ----
    {
        const int n4 = tid & 15, g = tid >> 4;      // g in 0..63, 16 d each
        const float4* w4 = reinterpret_cast<const float4*>(ew1);
        float4 acc = make_float4(0.f, 0.f, 0.f, 0.f);
        #pragma unroll 4
        for (int i = 0; i < 16; ++i) {
            const int d = g * 16 + i;
            const float4 wv = w4[d * 16 + n4];
            const float  f  = s_feat[d];
            acc.x = fmaf(f, wv.x, acc.x);
            acc.y = fmaf(f, wv.y, acc.y);
            acc.z = fmaf(f, wv.z, acc.z);
            acc.w = fmaf(f, wv.w, acc.w);
        }
        reinterpret_cast<float4*>(s_buf2)[g * 16 + n4] = acc; // float idx g*64+n
    }
    __syncthreads();

    // ---- reduces (parallel across thread ranges) ----
    if (tid < 128) {
        float v = 0.f;
        #pragma unroll
        for (int g = 0; g < 32; ++g) v += s_buf[g * 128 + tid];
        s_h1[tid] = fmaxf(v + sb1[tid], 0.0f);
    } else if (tid < 192) {
        const int n = tid - 128;
        float v = 0.f;
        #pragma unroll
        for (int g = 0; g < 64; ++g) v += s_buf2[g * 64 + n];
        s_eh[n] = fmaxf(v + eb1[n], 0.0f);
    }
    __syncthreads();

    // ---- layer 2: warp-per-output ----
    {
        const int w = tid >> 5, lane = tid & 31;
        if (w < 14) {
            float acc = 0.f;
            #pragma unroll
            for (int k = lane; k < 128; k += 32)
                acc = fmaf(s_h1[k], sw2[k * 14 + w], acc);
            #pragma unroll
            for (int off = 16; off > 0; off >>= 1)
                acc += __shfl_down_sync(0xffffffffu, acc, off);
            if (lane == 0) s_logit[w] = acc + sb2[w];
        } else if (w == 14) {
            #pragma unroll
            for (int j = 0; j < 3; ++j) {
                float acc = fmaf(s_eh[lane], ew2[lane * 3 + j],
                                 s_eh[lane + 32] * ew2[(lane + 32) * 3 + j]);
                #pragma unroll
                for (int off = 16; off > 0; off >>= 1)
                    acc += __shfl_down_sync(0xffffffffu, acc, off);
                if (lane == 0) s_eff[j] = acc + eb2[j];
            }
        }
    }
    __syncthreads();

    // Output layout (flat float32, reference tuple order):
    //   [0,512)     shift (B,8,2)   [512,2304)  dx_logits (B,8,7)
    //   [2304,4096) dy_logits       [4096,4352) sig(e0)*seen
    //   [4352,4608) sig(e1)*seen    [4608,4864) e2*seen
    const int ba = b * NA_ + a;

    if (tid < 7)              out[512  + ba * 7 + tid]       = s_logit[tid];
    if (tid >= 7 && tid < 14) out[2304 + ba * 7 + (tid - 7)] = s_logit[tid];

    if (tid == 0) {
        const float bins[7] = {-16.f, -8.f, -4.f, 0.f, 4.f, 8.f, 16.f};
        #pragma unroll
        for (int h = 0; h < 2; ++h) {
            const float* lg = &s_logit[h * 7];
            float mx = lg[0];
            #pragma unroll
            for (int j = 1; j < 7; ++j) mx = fmaxf(mx, lg[j]);
            float den = 0.f, num = 0.f;
            #pragma unroll
            for (int j = 0; j < 7; ++j) {
                const float e = __expf(lg[j] - mx);
                den += e;
                num += e * bins[j];
            }
            out[ba * 2 + h] = (num / den) * seen;
        }
        out[4096 + ba] = (1.0f / (1.0f + __expf(-s_eff[0]))) * seen;
        out[4352 + ba] = (1.0f / (1.0f + __expf(-s_eff[1]))) * seen;
        out[4608 + ba] = s_eff[2] * seen;
    }
}

// ---------------------------------------------------------------------------
extern "C" void kernel_launch(void* const* d_in, const int* in_sizes, int n_in,
                              void* d_out, int out_size)
{
    const float4* emb4 = (const float4*)d_in[0];
    const int*    act  = (const int*)d_in[1];
    const int*    mask = (const int*)d_in[2];
    const float* sw1 = (const float*)d_in[3];
    const float* sb1 = (const float*)d_in[4];
    const float* sw2 = (const float*)d_in[5];
    const float* sb2 = (const float*)d_in[6];
    const float* ew1 = (const float*)d_in[7];
    const float* eb1 = (const float*)d_in[8];
    const float* ew2 = (const float*)d_in[9];
    const float* eb2 = (const float*)d_in[10];
    float* out = (float*)d_out;

    accum_kernel<<<dim3(NCHUNK, B_), 256>>>(emb4, act, mask);
    head_kernel<<<dim3(NA_, B_), 1024>>>(sw1, sb1, sw2, sb2,
                                         ew1, eb1, ew2, eb2, out);
}

// round 10
// speedup vs baseline: 1.1840x; 1.1840x over previous
#include <cuda_runtime.h>
#include <math.h>

#define B_  32
#define L_  4096
#define D_  1024
#define D4_ (D_ / 4)           // 256 float4 per row
#define NA_ 8
#define NCHUNK 16
#define LCHUNK (L_ / NCHUNK)   // 256
#define NW_ 8                  // warps per accum block

// Partial sums per (b, l-chunk, action, d). 16.8 MB scratch (L2-resident).
__device__ float g_part[B_ * NCHUNK * NA_ * D_];
// Per (b, l-chunk, action) masked counts.
__device__ int   g_cnt [B_ * NCHUNK * NA_];

// ---------------------------------------------------------------------------
// Kernel 1: masked segmented sum into per-chunk partials.
// grid = (NCHUNK, B) = 512 blocks, 256 threads; thread owns one float4
// column. Rows stably partitioned by action via warp ballots; main loop is
// branchless with 4 loads in flight. emb is read once -> __ldcs (evict-first)
// keeps L2 free for the g_part scratch the head re-reads.
// (R8 geometry, measured 88.4 us.)
// ---------------------------------------------------------------------------
__global__ __launch_bounds__(256, 6)
void accum_kernel(const float4* __restrict__ emb4,
                  const int* __restrict__ actions,
                  const int* __restrict__ mask)
{
    const int chunk = blockIdx.x;
    const int b     = blockIdx.y;
    const int tid   = threadIdx.x;
    const int l0    = chunk * LCHUNK;
    const int w     = tid >> 5, lane = tid & 31;

    __shared__ short s_order[LCHUNK];
    __shared__ int   s_wcnt[NA_ * NW_];
    __shared__ int   s_woff[NA_ * NW_ + 1];

    // mask is bool upcast to a 4-byte type by the harness; nonzero = True.
    int act;
    {
        int a = actions[b * L_ + l0 + tid];
        int m = mask[b * L_ + l0 + tid];
        act = (m != 0) ? a : -1;
    }

    // Stable partition by action: warp ballots + popc ranks.
    const unsigned lt = (1u << lane) - 1u;
    int myrank = 0;
    #pragma unroll
    for (int aa = 0; aa < NA_; ++aa) {
        unsigned bal = __ballot_sync(0xffffffffu, act == aa);
        if (lane == 0) s_wcnt[aa * NW_ + w] = __popc(bal);
        if (act == aa) myrank = __popc(bal & lt);
    }
    __syncthreads();
    if (tid == 0) {
        int acc = 0;
        #pragma unroll
        for (int q = 0; q < NA_ * NW_; ++q) { s_woff[q] = acc; acc += s_wcnt[q]; }
        s_woff[NA_ * NW_] = acc;
    }
    __syncthreads();
    if (act >= 0) s_order[s_woff[act * NW_ + w] + myrank] = (short)tid;
    if (tid < NA_)
        g_cnt[(b * NCHUNK + chunk) * NA_ + tid] =
            s_woff[(tid + 1) * NW_] - s_woff[tid * NW_];
    __syncthreads();

    const float4* base = emb4 + ((size_t)b * L_ + l0) * D4_ + tid;
    float4* outp = reinterpret_cast<float4*>(g_part)
                   + (size_t)(b * NCHUNK + chunk) * NA_ * D4_ + tid;

    #pragma unroll 1
    for (int a = 0; a < NA_; ++a) {
        float4 acc = make_float4(0.f, 0.f, 0.f, 0.f);
        const int s = s_woff[a * NW_], e = s_woff[(a + 1) * NW_];
        int i = s;
        for (; i + 4 <= e; i += 4) {
            const float4 v0 = __ldcs(base + (int)s_order[i]     * D4_);
            const float4 v1 = __ldcs(base + (int)s_order[i + 1] * D4_);
            const float4 v2 = __ldcs(base + (int)s_order[i + 2] * D4_);
            const float4 v3 = __ldcs(base + (int)s_order[i + 3] * D4_);
            acc.x += (v0.x + v1.x) + (v2.x + v3.x);
            acc.y += (v0.y + v1.y) + (v2.y + v3.y);
            acc.z += (v0.z + v1.z) + (v2.z + v3.z);
            acc.w += (v0.w + v1.w) + (v2.w + v3.w);
        }
        for (; i < e; ++i) {
            const float4 v = __ldcs(base + (int)s_order[i] * D4_);
            acc.x += v.x; acc.y += v.y; acc.z += v.z; acc.w += v.w;
        }
        outp[a * D4_] = acc;
    }
}

// ---------------------------------------------------------------------------
// Kernel 2: head. grid = (NA, B) = 256 blocks, 1024 threads. Layer-1 uses
// float4 weight loads (4 neurons per thread) — 4x fewer L1 wavefronts.
// (R9 structure, measured 19.5 us with 2x partial traffic; NCHUNK=16 here.)
// ---------------------------------------------------------------------------
__global__ __launch_bounds__(1024)
void head_kernel(const float* __restrict__ sw1, const float* __restrict__ sb1,
                 const float* __restrict__ sw2, const float* __restrict__ sb2,
                 const float* __restrict__ ew1, const float* __restrict__ eb1,
                 const float* __restrict__ ew2, const float* __restrict__ eb2,
                 float* __restrict__ out)
{
    const int a   = blockIdx.x;
    const int b   = blockIdx.y;
    const int tid = threadIdx.x;

    __shared__ float s_feat[D_];       // 4 KB
    __shared__ float s_buf [4096];     // 16 KB (feats partials, then MLP1 partials)
    __shared__ float s_buf2[4096];     // 16 KB (effect-MLP partials)
    __shared__ float s_h1[128];
    __shared__ float s_eh[64];
    __shared__ float s_logit[14];
    __shared__ float s_eff[3];
    __shared__ float s_scal[2];        // [0] = inv_cnt, [1] = seen

    // ---- counts ----
    if (tid == 0) {
        int c = 0;
        #pragma unroll
        for (int ch = 0; ch < NCHUNK; ++ch)
            c += g_cnt[(b * NCHUNK + ch) * NA_ + a];
        s_scal[0] = 1.0f / fmaxf((float)c, 1.0f);
        s_scal[1] = (c > 0) ? 1.0f : 0.0f;
    }

    // ---- feats partials: col4 = tid&255, chunk-group cg = tid>>8 (4 x 4) ----
    {
        const int col4 = tid & 255, cg = tid >> 8;
        const float4* gp4 = reinterpret_cast<const float4*>(g_part)
                            + ((size_t)b * NCHUNK * NA_ + a) * D4_ + col4;
        float4 s = make_float4(0.f, 0.f, 0.f, 0.f);
        #pragma unroll
        for (int ch = 0; ch < NCHUNK / 4; ++ch) {   // 4 chunks per group
            const float4 v = gp4[(size_t)(cg * (NCHUNK / 4) + ch) * NA_ * D4_];
            s.x += v.x; s.y += v.y; s.z += v.z; s.w += v.w;
        }
        reinterpret_cast<float4*>(s_buf)[cg * 256 + col4] = s;
    }
    __syncthreads();
    const float inv_cnt = s_scal[0];
    const float seen    = s_scal[1];
    {
        // element (cg, d) lives at s_buf[cg*1024 + d]
        float v = (s_buf[tid] + s_buf[1024 + tid])
                + (s_buf[2048 + tid] + s_buf[3072 + tid]);
        s_feat[tid] = v * inv_cnt;
    }
    __syncthreads();

    // ---- MLP1 layer 1 partials: 32 neuron-quads x 32 d-groups ----
    {
        const int n4 = tid & 31, g = tid >> 5;      // g in 0..31, 32 d each
        const float4* w4 = reinterpret_cast<const float4*>(sw1);
        float4 acc = make_float4(0.f, 0.f, 0.f, 0.f);
        #pragma unroll 4
        for (int i = 0; i < 32; ++i) {
            const int d = g * 32 + i;
            const float4 wv = w4[d * 32 + n4];
            const float  f  = s_feat[d];
            acc.x = fmaf(f, wv.x, acc.x);
            acc.y = fmaf(f, wv.y, acc.y);
            acc.z = fmaf(f, wv.z, acc.z);
            acc.w = fmaf(f, wv.w, acc.w);
        }
        reinterpret_cast<float4*>(s_buf)[g * 32 + n4] = acc;  // float idx g*128+n
    }
    // ---- effect MLP layer 1 partials: 16 neuron-quads x 64 d-groups ----
    {
        const int n4 = tid & 15, g = tid >> 4;      // g in 0..63, 16 d each
        const float4* w4 = reinterpret_cast<const float4*>(ew1);
        float4 acc = make_float4(0.f, 0.f, 0.f, 0.f);
        #pragma unroll 4
        for (int i = 0; i < 16; ++i) {
            const int d = g * 16 + i;
            const float4 wv = w4[d * 16 + n4];
            const float  f  = s_feat[d];
            acc.x = fmaf(f, wv.x, acc.x);
            acc.y = fmaf(f, wv.y, acc.y);
            acc.z = fmaf(f, wv.z, acc.z);
            acc.w = fmaf(f, wv.w, acc.w);
        }
        reinterpret_cast<float4*>(s_buf2)[g * 16 + n4] = acc; // float idx g*64+n
    }
    __syncthreads();

    // ---- reduces (parallel across thread ranges) ----
    if (tid < 128) {
        float v = 0.f;
        #pragma unroll
        for (int g = 0; g < 32; ++g) v += s_buf[g * 128 + tid];
        s_h1[tid] = fmaxf(v + sb1[tid], 0.0f);
    } else if (tid < 192) {
        const int n = tid - 128;
        float v = 0.f;
        #pragma unroll
        for (int g = 0; g < 64; ++g) v += s_buf2[g * 64 + n];
        s_eh[n] = fmaxf(v + eb1[n], 0.0f);
    }
    __syncthreads();

    // ---- layer 2: warp-per-output ----
    {
        const int w = tid >> 5, lane = tid & 31;
        if (w < 14) {
            float acc = 0.f;
            #pragma unroll
            for (int k = lane; k < 128; k += 32)
                acc = fmaf(s_h1[k], sw2[k * 14 + w], acc);
            #pragma unroll
            for (int off = 16; off > 0; off >>= 1)
                acc += __shfl_down_sync(0xffffffffu, acc, off);
            if (lane == 0) s_logit[w] = acc + sb2[w];
        } else if (w == 14) {
            #pragma unroll
            for (int j = 0; j < 3; ++j) {
                float acc = fmaf(s_eh[lane], ew2[lane * 3 + j],
                                 s_eh[lane + 32] * ew2[(lane + 32) * 3 + j]);
                #pragma unroll
                for (int off = 16; off > 0; off >>= 1)
                    acc += __shfl_down_sync(0xffffffffu, acc, off);
                if (lane == 0) s_eff[j] = acc + eb2[j];
            }
        }
    }
    __syncthreads();

    // Output layout (flat float32, reference tuple order):
    //   [0,512)     shift (B,8,2)   [512,2304)  dx_logits (B,8,7)
    //   [2304,4096) dy_logits       [4096,4352) sig(e0)*seen
    //   [4352,4608) sig(e1)*seen    [4608,4864) e2*seen
    const int ba = b * NA_ + a;

    if (tid < 7)              out[512  + ba * 7 + tid]       = s_logit[tid];
    if (tid >= 7 && tid < 14) out[2304 + ba * 7 + (tid - 7)] = s_logit[tid];

    if (tid == 0) {
        const float bins[7] = {-16.f, -8.f, -4.f, 0.f, 4.f, 8.f, 16.f};
        #pragma unroll
        for (int h = 0; h < 2; ++h) {
            const float* lg = &s_logit[h * 7];
            float mx = lg[0];
            #pragma unroll
            for (int j = 1; j < 7; ++j) mx = fmaxf(mx, lg[j]);
            float den = 0.f, num = 0.f;
            #pragma unroll
            for (int j = 0; j < 7; ++j) {
                const float e = __expf(lg[j] - mx);
                den += e;
                num += e * bins[j];
            }
            out[ba * 2 + h] = (num / den) * seen;
        }
        out[4096 + ba] = (1.0f / (1.0f + __expf(-s_eff[0]))) * seen;
        out[4352 + ba] = (1.0f / (1.0f + __expf(-s_eff[1]))) * seen;
        out[4608 + ba] = s_eff[2] * seen;
    }
}

// ---------------------------------------------------------------------------
extern "C" void kernel_launch(void* const* d_in, const int* in_sizes, int n_in,
                              void* d_out, int out_size)
{
    const float4* emb4 = (const float4*)d_in[0];
    const int*    act  = (const int*)d_in[1];
    const int*    mask = (const int*)d_in[2];
    const float* sw1 = (const float*)d_in[3];
    const float* sb1 = (const float*)d_in[4];
    const float* sw2 = (const float*)d_in[5];
    const float* sb2 = (const float*)d_in[6];
    const float* ew1 = (const float*)d_in[7];
    const float* eb1 = (const float*)d_in[8];
    const float* ew2 = (const float*)d_in[9];
    const float* eb2 = (const float*)d_in[10];
    float* out = (float*)d_out;

    accum_kernel<<<dim3(NCHUNK, B_), 256>>>(emb4, act, mask);
    head_kernel<<<dim3(NA_, B_), 1024>>>(sw1, sb1, sw2, sb2,
                                         ew1, eb1, ew2, eb2, out);
}

// round 11
// speedup vs baseline: 1.1987x; 1.0124x over previous
#include <cuda_runtime.h>
#include <math.h>

#define B_  32
#define L_  4096
#define D_  1024
#define D4_ (D_ / 4)           // 256 float4 per row
#define NA_ 8
#define NCHUNK 16
#define LCHUNK (L_ / NCHUNK)   // 256
#define NWA_ 4                 // warps per accum block (128 threads)
#define NPASS 2                // row passes (256 rows / 128 threads)
#define DH4_ 128               // float4 columns per D-half

// Partial sums per (b, l-chunk, action, d). 16.8 MB scratch (L2-resident).
__device__ float g_part[B_ * NCHUNK * NA_ * D_];
// Per (b, l-chunk, action) masked counts.
__device__ int   g_cnt [B_ * NCHUNK * NA_];

// ---------------------------------------------------------------------------
// Kernel 1: masked segmented sum into per-chunk partials.
// grid = (NCHUNK, B, 2) = 1024 blocks x 128 threads; blockIdx.z selects the
// D-half this block owns (128 float4 columns). 1024 blocks / 148 SMs kills
// the 3-vs-4 blocks/SM straggler tail of the 512-block version while keeping
// write traffic and action-group sizes identical. Rows stably partitioned by
// action via pass-major warp ballots; main loop branchless, 4 loads in
// flight, __ldcs (emb read exactly once).
// ---------------------------------------------------------------------------
__global__ __launch_bounds__(128, 12)
void accum_kernel(const float4* __restrict__ emb4,
                  const int* __restrict__ actions,
                  const int* __restrict__ mask)
{
    const int chunk = blockIdx.x;
    const int b     = blockIdx.y;
    const int dh    = blockIdx.z;          // 0 or 1: D-half
    const int tid   = threadIdx.x;         // 0..127
    const int l0    = chunk * LCHUNK;
    const int w     = tid >> 5, lane = tid & 31;

    __shared__ short s_order[LCHUNK];
    __shared__ int   s_wcnt[NA_ * NPASS * NWA_];
    __shared__ int   s_woff[NA_ * NPASS * NWA_ + 1];

    // mask is bool upcast to a 4-byte type by the harness; nonzero = True.
    int act[NPASS];
    #pragma unroll
    for (int p = 0; p < NPASS; ++p) {
        const int row = p * 128 + tid;
        int a = actions[b * L_ + l0 + row];
        int m = mask[b * L_ + l0 + row];
        act[p] = (m != 0) ? a : -1;
    }

    // Stable partition: slot index q = aa*(NPASS*NWA_) + p*NWA_ + w keeps
    // ascending-row order within each action (pass-major, then warp, then lane).
    const unsigned lt = (1u << lane) - 1u;
    int myrank[NPASS];
    #pragma unroll
    for (int p = 0; p < NPASS; ++p) {
        myrank[p] = 0;
        #pragma unroll
        for (int aa = 0; aa < NA_; ++aa) {
            unsigned bal = __ballot_sync(0xffffffffu, act[p] == aa);
            if (lane == 0) s_wcnt[aa * (NPASS * NWA_) + p * NWA_ + w] = __popc(bal);
            if (act[p] == aa) myrank[p] = __popc(bal & lt);
        }
    }
    __syncthreads();
    if (tid == 0) {
        int acc = 0;
        #pragma unroll
        for (int q = 0; q < NA_ * NPASS * NWA_; ++q) { s_woff[q] = acc; acc += s_wcnt[q]; }
        s_woff[NA_ * NPASS * NWA_] = acc;
    }
    __syncthreads();
    #pragma unroll
    for (int p = 0; p < NPASS; ++p)
        if (act[p] >= 0)
            s_order[s_woff[act[p] * (NPASS * NWA_) + p * NWA_ + w] + myrank[p]]
                = (short)(p * 128 + tid);
    if (dh == 0 && tid < NA_)
        g_cnt[(b * NCHUNK + chunk) * NA_ + tid] =
            s_woff[(tid + 1) * (NPASS * NWA_)] - s_woff[tid * (NPASS * NWA_)];
    __syncthreads();

    const float4* base = emb4 + ((size_t)b * L_ + l0) * D4_ + dh * DH4_ + tid;
    float4* outp = reinterpret_cast<float4*>(g_part)
                   + (size_t)(b * NCHUNK + chunk) * NA_ * D4_ + dh * DH4_ + tid;

    #pragma unroll 1
    for (int a = 0; a < NA_; ++a) {
        float4 acc = make_float4(0.f, 0.f, 0.f, 0.f);
        const int s = s_woff[a * (NPASS * NWA_)], e = s_woff[(a + 1) * (NPASS * NWA_)];
        int i = s;
        for (; i + 4 <= e; i += 4) {
            const float4 v0 = __ldcs(base + (int)s_order[i]     * D4_);
            const float4 v1 = __ldcs(base + (int)s_order[i + 1] * D4_);
            const float4 v2 = __ldcs(base + (int)s_order[i + 2] * D4_);
            const float4 v3 = __ldcs(base + (int)s_order[i + 3] * D4_);
            acc.x += (v0.x + v1.x) + (v2.x + v3.x);
            acc.y += (v0.y + v1.y) + (v2.y + v3.y);
            acc.z += (v0.z + v1.z) + (v2.z + v3.z);
            acc.w += (v0.w + v1.w) + (v2.w + v3.w);
        }
        for (; i < e; ++i) {
            const float4 v = __ldcs(base + (int)s_order[i] * D4_);
            acc.x += v.x; acc.y += v.y; acc.z += v.z; acc.w += v.w;
        }
        outp[a * D4_] = acc;
    }
}

// ---------------------------------------------------------------------------
// Kernel 2: head. grid = (NA, B) = 256 blocks, 1024 threads. Layer-1 uses
// float4 weight loads (4 neurons per thread). (Measured 17.0 us — unchanged.)
// ---------------------------------------------------------------------------
__global__ __launch_bounds__(1024)
void head_kernel(const float* __restrict__ sw1, const float* __restrict__ sb1,
                 const float* __restrict__ sw2, const float* __restrict__ sb2,
                 const float* __restrict__ ew1, const float* __restrict__ eb1,
                 const float* __restrict__ ew2, const float* __restrict__ eb2,
                 float* __restrict__ out)
{
    const int a   = blockIdx.x;
    const int b   = blockIdx.y;
    const int tid = threadIdx.x;

    __shared__ float s_feat[D_];       // 4 KB
    __shared__ float s_buf [4096];     // 16 KB (feats partials, then MLP1 partials)
    __shared__ float s_buf2[4096];     // 16 KB (effect-MLP partials)
    __shared__ float s_h1[128];
    __shared__ float s_eh[64];
    __shared__ float s_logit[14];
    __shared__ float s_eff[3];
    __shared__ float s_scal[2];        // [0] = inv_cnt, [1] = seen

    // ---- counts ----
    if (tid == 0) {
        int c = 0;
        #pragma unroll
        for (int ch = 0; ch < NCHUNK; ++ch)
            c += g_cnt[(b * NCHUNK + ch) * NA_ + a];
        s_scal[0] = 1.0f / fmaxf((float)c, 1.0f);
        s_scal[1] = (c > 0) ? 1.0f : 0.0f;
    }

    // ---- feats partials: col4 = tid&255, chunk-group cg = tid>>8 (4 x 4) ----
    {
        const int col4 = tid & 255, cg = tid >> 8;
        const float4* gp4 = reinterpret_cast<const float4*>(g_part)
                            + ((size_t)b * NCHUNK * NA_ + a) * D4_ + col4;
        float4 s = make_float4(0.f, 0.f, 0.f, 0.f);
        #pragma unroll
        for (int ch = 0; ch < NCHUNK / 4; ++ch) {   // 4 chunks per group
            const float4 v = gp4[(size_t)(cg * (NCHUNK / 4) + ch) * NA_ * D4_];
            s.x += v.x; s.y += v.y; s.z += v.z; s.w += v.w;
        }
        reinterpret_cast<float4*>(s_buf)[cg * 256 + col4] = s;
    }
    __syncthreads();
    const float inv_cnt = s_scal[0];
    const float seen    = s_scal[1];
    {
        // element (cg, d) lives at s_buf[cg*1024 + d]
        float v = (s_buf[tid] + s_buf[1024 + tid])
                + (s_buf[2048 + tid] + s_buf[3072 + tid]);
        s_feat[tid] = v * inv_cnt;
    }
    __syncthreads();

    // ---- MLP1 layer 1 partials: 32 neuron-quads x 32 d-groups ----
    {
        const int n4 = tid & 31, g = tid >> 5;      // g in 0..31, 32 d each
        const float4* w4 = reinterpret_cast<const float4*>(sw1);
        float4 acc = make_float4(0.f, 0.f, 0.f, 0.f);
        #pragma unroll 4
        for (int i = 0; i < 32; ++i) {
            const int d = g * 32 + i;
            const float4 wv = w4[d * 32 + n4];
            const float  f  = s_feat[d];
            acc.x = fmaf(f, wv.x, acc.x);
            acc.y = fmaf(f, wv.y, acc.y);
            acc.z = fmaf(f, wv.z, acc.z);
            acc.w = fmaf(f, wv.w, acc.w);
        }
        reinterpret_cast<float4*>(s_buf)[g * 32 + n4] = acc;  // float idx g*128+n
    }
    // ---- effect MLP layer 1 partials: 16 neuron-quads x 64 d-groups ----
    {
        const int n4 = tid & 15, g = tid >> 4;      // g in 0..63, 16 d each
        const float4* w4 = reinterpret_cast<const float4*>(ew1);
        float4 acc = make_float4(0.f, 0.f, 0.f, 0.f);
        #pragma unroll 4
        for (int i = 0; i < 16; ++i) {
            const int d = g * 16 + i;
            const float4 wv = w4[d * 16 + n4];
            const float  f  = s_feat[d];
            acc.x = fmaf(f, wv.x, acc.x);
            acc.y = fmaf(f, wv.y, acc.y);
            acc.z = fmaf(f, wv.z, acc.z);
            acc.w = fmaf(f, wv.w, acc.w);
        }
        reinterpret_cast<float4*>(s_buf2)[g * 16 + n4] = acc; // float idx g*64+n
    }
    __syncthreads();

    // ---- reduces (parallel across thread ranges) ----
    if (tid < 128) {
        float v = 0.f;
        #pragma unroll
        for (int g = 0; g < 32; ++g) v += s_buf[g * 128 + tid];
        s_h1[tid] = fmaxf(v + sb1[tid], 0.0f);
    } else if (tid < 192) {
        const int n = tid - 128;
        float v = 0.f;
        #pragma unroll
        for (int g = 0; g < 64; ++g) v += s_buf2[g * 64 + n];
        s_eh[n] = fmaxf(v + eb1[n], 0.0f);
    }
    __syncthreads();

    // ---- layer 2: warp-per-output ----
    {
        const int w = tid >> 5, lane = tid & 31;
        if (w < 14) {
            float acc = 0.f;
            #pragma unroll
            for (int k = lane; k < 128; k += 32)
                acc = fmaf(s_h1[k], sw2[k * 14 + w], acc);
            #pragma unroll
            for (int off = 16; off > 0; off >>= 1)
                acc += __shfl_down_sync(0xffffffffu, acc, off);
            if (lane == 0) s_logit[w] = acc + sb2[w];
        } else if (w == 14) {
            #pragma unroll
            for (int j = 0; j < 3; ++j) {
                float acc = fmaf(s_eh[lane], ew2[lane * 3 + j],
                                 s_eh[lane + 32] * ew2[(lane + 32) * 3 + j]);
                #pragma unroll
                for (int off = 16; off > 0; off >>= 1)
                    acc += __shfl_down_sync(0xffffffffu, acc, off);
                if (lane == 0) s_eff[j] = acc + eb2[j];
            }
        }
    }
    __syncthreads();

    // Output layout (flat float32, reference tuple order):
    //   [0,512)     shift (B,8,2)   [512,2304)  dx_logits (B,8,7)
    //   [2304,4096) dy_logits       [4096,4352) sig(e0)*seen
    //   [4352,4608) sig(e1)*seen    [4608,4864) e2*seen
    const int ba = b * NA_ + a;

    if (tid < 7)              out[512  + ba * 7 + tid]       = s_logit[tid];
    if (tid >= 7 && tid < 14) out[2304 + ba * 7 + (tid - 7)] = s_logit[tid];

    if (tid == 0) {
        const float bins[7] = {-16.f, -8.f, -4.f, 0.f, 4.f, 8.f, 16.f};
        #pragma unroll
        for (int h = 0; h < 2; ++h) {
            const float* lg = &s_logit[h * 7];
            float mx = lg[0];
            #pragma unroll
            for (int j = 1; j < 7; ++j) mx = fmaxf(mx, lg[j]);
            float den = 0.f, num = 0.f;
            #pragma unroll
            for (int j = 0; j < 7; ++j) {
                const float e = __expf(lg[j] - mx);
                den += e;
                num += e * bins[j];
            }
            out[ba * 2 + h] = (num / den) * seen;
        }
        out[4096 + ba] = (1.0f / (1.0f + __expf(-s_eff[0]))) * seen;
        out[4352 + ba] = (1.0f / (1.0f + __expf(-s_eff[1]))) * seen;
        out[4608 + ba] = s_eff[2] * seen;
    }
}

// ---------------------------------------------------------------------------
extern "C" void kernel_launch(void* const* d_in, const int* in_sizes, int n_in,
                              void* d_out, int out_size)
{
    const float4* emb4 = (const float4*)d_in[0];
    const int*    act  = (const int*)d_in[1];
    const int*    mask = (const int*)d_in[2];
    const float* sw1 = (const float*)d_in[3];
    const float* sb1 = (const float*)d_in[4];
    const float* sw2 = (const float*)d_in[5];
    const float* sb2 = (const float*)d_in[6];
    const float* ew1 = (const float*)d_in[7];
    const float* eb1 = (const float*)d_in[8];
    const float* ew2 = (const float*)d_in[9];
    const float* eb2 = (const float*)d_in[10];
    float* out = (float*)d_out;

    accum_kernel<<<dim3(NCHUNK, B_, 2), 128>>>(emb4, act, mask);
    head_kernel<<<dim3(NA_, B_), 1024>>>(sw1, sb1, sw2, sb2,
                                         ew1, eb1, ew2, eb2, out);
}